// round 15
// baseline (speedup 1.0000x reference)
#include <cuda_runtime.h>
#include <cuda_bf16.h>

// RocketConv: 84 ternary dilated depthwise kernels (alpha=-1, beta=2 at 3 taps).
// y_k[t] = -S(t) + 3*(s_a + s_b + s_c),  s_j = x[t + 4j - 16],  S = sum_j s_j
// Output layout (reference's double reshape) is flat (B, C, K, T):
//   out[((b*16 + c)*84 + k)*4096 + t]
//
// R13 vs R5 (best, 53.7us): drop the smem staging tile. Input x is 4 MB and
// fully L2-resident (re-read every replay), so the 9 taps per thread load
// directly via __ldg float2 (8B-aligned, predicated zero-fill at edges).
// Removes the LDG->STS->bar->LDS prologue from all 4096 blocks so streaming
// stores start earlier. Everything else is the certified memory-wall config:
// __stcs STG.64 stream at 6.55 TB/s wall-effective (~82% HBM3e spec).

#define T_LEN    4096
#define SEG      256
#define NTHREADS 128

__global__ __launch_bounds__(NTHREADS, 12)
void rocketconv_kernel(const float* __restrict__ x, float* __restrict__ out) {
    const int row = blockIdx.y;                 // b*16 + c
    const int seg = blockIdx.x * SEG;           // start t of this segment
    const float* __restrict__ xrow = x + (size_t)row * T_LEN;

    // Thread handles t0, t0+1 with t0 = seg + 2*tid.
    // Tap j (for both elements) = x[t0 + 4j - 16 .. +1]: float2 at an even
    // index -> 8-byte aligned. Zero-fill outside [0, T_LEN).
    const int t0 = seg + 2 * threadIdx.x;

    float2 t9[9];
    #pragma unroll
    for (int j = 0; j < 9; j++) {
        const int g = t0 + 4 * j - 16;
        if (g >= 0 && g + 1 < T_LEN) {
            t9[j] = __ldg(reinterpret_cast<const float2*>(xrow + g));
        } else {
            // Row edges only (first/last segment of each row).
            float a = (g >= 0 && g < T_LEN)         ? __ldg(xrow + g)     : 0.0f;
            float b = (g + 1 >= 0 && g + 1 < T_LEN) ? __ldg(xrow + g + 1) : 0.0f;
            t9[j] = make_float2(a, b);
        }
    }

    float Sx = 0.f, Sy = 0.f;
    #pragma unroll
    for (int j = 0; j < 9; j++) { Sx += t9[j].x; Sy += t9[j].y; }
    const float nSx = -Sx, nSy = -Sy;

    // Output base for k=0 at this thread's t0; k-stride = 4096 floats = 2048 float2.
    float2* __restrict__ obase = reinterpret_cast<float2*>(
        out + (size_t)row * 84 * T_LEN + seg) + threadIdx.x;

    // Triangular combo enumeration in lex order; pair-sum reuse amortizes the
    // 84 outputs to ~1 ADD + 1 FMA per element per lane.
    int k = 0;
    #pragma unroll
    for (int a = 0; a < 9; a++) {
        #pragma unroll
        for (int b = a + 1; b < 9; b++) {
            const float px = t9[a].x + t9[b].x;
            const float py = t9[a].y + t9[b].y;
            #pragma unroll
            for (int c = b + 1; c < 9; c++) {
                float2 r;
                r.x = fmaf(3.0f, px + t9[c].x, nSx);
                r.y = fmaf(3.0f, py + t9[c].y, nSy);
                // Streaming store: write-once 352 MB output, evict-first in L2.
                __stcs(obase + (size_t)k * (T_LEN / 2), r);
                k++;
            }
        }
    }
}

extern "C" void kernel_launch(void* const* d_in, const int* in_sizes, int n_in,
                              void* d_out, int out_size) {
    const float* x = (const float*)d_in[0];
    float* out = (float*)d_out;
    dim3 grid(T_LEN / SEG, 16 * 16);   // (16, 256)
    rocketconv_kernel<<<grid, NTHREADS>>>(x, out);
}